// round 14
// baseline (speedup 1.0000x reference)
#include <cuda_runtime.h>
#include <cstdint>

// ============================================================================
// tf32 mma.sync implicit-GEMM 3x3 SAME conv + bias, x-row-resident,
// A-register-reuse, PERSISTENT version (fixed: no runtime device queries,
// no static state — sms hardcoded to 148).
// Grid = 148; each CTA processes full tiles bid + r*148 (128k x 4p x 64q),
// then the remainder tiles are split into 32-q half-tiles to shrink the tail
// wave. Next tile's chunk 0/1 prefetched during current tile's chunk 2/3 so
// epilogue overlaps with fills. Inner loop identical to R12.
// ============================================================================

#define NSTAGES 36
#define SMS     148

// [stage36][j4][mtile8][lane32][reg4] tf32 bits
static __device__ __align__(128) unsigned WtFrag[NSTAGES * 4 * 8 * 32 * 4];

__global__ void prepack_kernel(const float* __restrict__ W) {
    int idx = blockIdx.x * 256 + threadIdx.x;
    if (idx >= NSTAGES * 4096) return;
    int reg  = idx & 3;
    int lane = (idx >> 2) & 31;
    int mt   = (idx >> 7) & 7;
    int j    = (idx >> 10) & 3;
    int s    = idx >> 12;            // stage = shift*4 + chunk
    int shift = s >> 2;
    int chunk = s & 3;
    int dr = (reg & 1) ? 8 : 0;
    int dk = (reg & 2) ? 4 : 0;
    int r  = (lane >> 2) + dr;
    int kc = (lane & 3) + dk;
    int k  = mt * 16 + r;
    int c  = chunk * 32 + j * 8 + kc;
    float v = W[k * 1152 + c * 9 + shift];
    unsigned u;
    asm("cvt.rna.tf32.f32 %0, %1;" : "=r"(u) : "f"(v));
    WtFrag[idx] = u;
}

// x strip: [c 0..31][row 0..5][col 0..75]; data cols 4..67 (q+4), halos 3 & 68.
#define XS_PITCH  76
#define XS_ROWS   6
#define XS_BUF_F  (32 * XS_ROWS * XS_PITCH)
#define XS_BUF_B  (XS_BUF_F * 4)              // 58368 bytes
#define DYN_SMEM  (2 * XS_BUF_B)              // 116736

__device__ __forceinline__ uint32_t smem_u32(const void* p) {
    uint32_t a;
    asm("{ .reg .u64 t; cvta.to.shared.u64 t, %1; cvt.u32.u64 %0, t; }" : "=r"(a) : "l"(p));
    return a;
}

__device__ __forceinline__ void mma_tf32(float* c, const unsigned* a, const unsigned* b) {
    asm volatile(
        "mma.sync.aligned.m16n8k8.row.col.f32.tf32.tf32.f32 "
        "{%0,%1,%2,%3}, {%4,%5,%6,%7}, {%8,%9}, {%0,%1,%2,%3};"
        : "+f"(c[0]), "+f"(c[1]), "+f"(c[2]), "+f"(c[3])
        : "r"(a[0]), "r"(a[1]), "r"(a[2]), "r"(a[3]), "r"(b[0]), "r"(b[1]));
}

#define LDG_A4(dst, ptr) \
    asm volatile("ld.global.nc.v4.u32 {%0,%1,%2,%3}, [%4];" \
                 : "=r"((dst)[0]), "=r"((dst)[1]), "=r"((dst)[2]), "=r"((dst)[3]) \
                 : "l"(ptr))

__global__ __launch_bounds__(256, 1)
void conv_mma_kernel(const float* __restrict__ x,
                     const float* __restrict__ per,
                     float* __restrict__ out) {
    extern __shared__ char smem[];
    const uint32_t sb = smem_u32(smem);

    const int tid  = threadIdx.x;
    const int lane = tid & 31;
    const int w    = tid >> 5;
    const int wm   = w >> 2;           // 0..1 : k base wm*64
    const int wn   = w & 3;            // 0..3 : p-row index within CTA
    const int gid  = lane >> 2;        // 0..7
    const int tig  = lane & 3;         // 0..3
    const int bid  = blockIdx.x;

    const int R   = 512 / SMS;         // 3 full-tile rounds
    const int rem = 512 - R * SMS;     // 68 tiles split into halves

    // ---- zero halo columns (cols 3 and 68 of every (c,row), both buffers) ----
    for (int idx = tid; idx < 2 * 32 * XS_ROWS; idx += 256) {
        const int buf = idx >= 32 * XS_ROWS;
        const int rm  = buf ? idx - 32 * XS_ROWS : idx;
        const uint32_t a = sb + buf * XS_BUF_B + rm * (XS_PITCH * 4);
        asm volatile("st.shared.f32 [%0], %1;" :: "r"(a + 3 * 4), "f"(0.f));
        asm volatile("st.shared.f32 [%0], %1;" :: "r"(a + 68 * 4), "f"(0.f));
    }

    // ---- prefetch thread mapping ----
    const int f_c  = tid >> 3;          // 0..31 c within chunk
    const int f_q0 = (tid & 7) << 3;    // 0,8,..,56

    auto prefetch = [&](int tile, int chunk, int buf) {
        const int tn  = tile >> 4;
        const int tp0 = (tile & 15) << 2;
        const float* srcc = x + (size_t)(tn * 128 + (chunk << 5) + f_c) * 4096 + f_q0;
        const uint32_t dstc = sb + buf * XS_BUF_B +
                              ((f_c * XS_ROWS) * XS_PITCH + 4 + f_q0) * 4;
        #pragma unroll
        for (int r = 0; r < XS_ROWS; r++) {
            const int row = tp0 - 1 + r;
            const int pb = ((unsigned)row < 64u) ? 16 : 0;
            const float* src = srcc + row * 64;
            const uint32_t dst = dstc + r * (XS_PITCH * 4);
            asm volatile("cp.async.cg.shared.global [%0], [%1], 16, %2;"
                         :: "r"(dst), "l"(src), "r"(pb));
            asm volatile("cp.async.cg.shared.global [%0], [%1], 16, %2;"
                         :: "r"(dst + 16), "l"(src + 4), "r"(pb));
        }
        asm volatile("cp.async.commit_group;");
    };

    // unit u -> (tile, nx range); full tiles for u < R, then 32-q half tiles
    auto unit_get = [&](int u, int& tile, int& nxlo, int& nxhi) -> bool {
        if (u < R) { tile = bid + u * SMS; nxlo = 0; nxhi = 2; return true; }
        int h = bid + (u - R) * SMS;
        if (h < 2 * rem) { tile = R * SMS + (h >> 1); nxlo = h & 1; nxhi = nxlo + 1; return true; }
        return false;
    };

    int tile, nxlo, nxhi;
    bool valid = unit_get(0, tile, nxlo, nxhi);
    if (valid) { prefetch(tile, 0, 0); prefetch(tile, 1, 1); }

    for (int u = 0; valid; u++) {
        int ntile, nnxlo, nnxhi;
        const bool nvalid = unit_get(u + 1, ntile, nnxlo, nnxhi);

        const int n  = tile >> 4;
        const int p0 = (tile & 15) << 2;
        const bool do0 = (nxlo == 0);
        const bool do1 = (nxhi == 2);

        float acc[2][4][4][4];
        #pragma unroll
        for (int nx = 0; nx < 2; nx++)
            #pragma unroll
            for (int mt = 0; mt < 4; mt++)
                #pragma unroll
                for (int nt = 0; nt < 4; nt++)
                    #pragma unroll
                    for (int e = 0; e < 4; e++) acc[nx][mt][nt][e] = 0.f;

        for (int chunk = 0; chunk < 4; chunk++) {
            if (chunk == 3 && !nvalid) asm volatile("cp.async.wait_group 0;");
            else                       asm volatile("cp.async.wait_group 1;");
            __syncthreads();

            const uint32_t xb = sb + (chunk & 1) * XS_BUF_B;
            const uint32_t bbase = xb + ((tig * XS_ROWS + wn) * XS_PITCH + 4 + gid) * 4;
            const uint4* abase = (const uint4*)WtFrag + (chunk << 10) + (wm << 7) + lane;

            unsigned areg[2][4][4];
            #pragma unroll
            for (int mt = 0; mt < 4; mt++)
                LDG_A4(areg[0][mt], abase + mt * 32);

            #pragma unroll
            for (int jj = 0; jj < 36; jj++) {
                const int shift = jj >> 2, j = jj & 3;
                const int kh = shift / 3, kw = shift - 3 * kh;
                const int cur = jj & 1, nxt = cur ^ 1;

                const int jn = jj + 1;
                const int aoff = (jn >> 2) * 4096 + (jn & 3) * 256;  // uint4 units

                if (jj < 35) {
                    LDG_A4(areg[nxt][0], abase + aoff + 0 * 32);
                    LDG_A4(areg[nxt][1], abase + aoff + 1 * 32);
                }

                const uint32_t bsj = bbase + (kh * XS_PITCH + kw - 1) * 4 + j * 14592;

                if (do0) {
                    const uint32_t bq = bsj;
                    unsigned b[4][2];
                    #pragma unroll
                    for (int nt = 0; nt < 4; nt++) {
                        asm volatile("ld.shared.b32 %0, [%1];" : "=r"(b[nt][0])
                                     : "r"(bq + (nt << 5)));
                        asm volatile("ld.shared.b32 %0, [%1];" : "=r"(b[nt][1])
                                     : "r"(bq + (nt << 5) + 7296));
                    }
                    #pragma unroll
                    for (int mt = 0; mt < 4; mt++)
                        #pragma unroll
                        for (int nt = 0; nt < 4; nt++)
                            mma_tf32(acc[0][mt][nt], areg[cur][mt], b[nt]);
                }

                if (jj < 35) {
                    LDG_A4(areg[nxt][2], abase + aoff + 2 * 32);
                    LDG_A4(areg[nxt][3], abase + aoff + 3 * 32);
                }

                if (do1) {
                    const uint32_t bq = bsj + 128;
                    unsigned b[4][2];
                    #pragma unroll
                    for (int nt = 0; nt < 4; nt++) {
                        asm volatile("ld.shared.b32 %0, [%1];" : "=r"(b[nt][0])
                                     : "r"(bq + (nt << 5)));
                        asm volatile("ld.shared.b32 %0, [%1];" : "=r"(b[nt][1])
                                     : "r"(bq + (nt << 5) + 7296));
                    }
                    #pragma unroll
                    for (int mt = 0; mt < 4; mt++)
                        #pragma unroll
                        for (int nt = 0; nt < 4; nt++)
                            mma_tf32(acc[1][mt][nt], areg[cur][mt], b[nt]);
                }
            }

            __syncthreads();
            if (chunk < 2)       prefetch(tile, chunk + 2, chunk & 1);
            else if (nvalid)     prefetch(ntile, chunk - 2, chunk & 1);
        }

        // ---- epilogue: +perturbs, store (overlaps with next tile's fills) ----
        const size_t nbase = (size_t)n * 128 * 4096;
        const int prow = p0 + wn;
        #pragma unroll
        for (int nx = 0; nx < 2; nx++) {
            if ((nx == 0 && !do0) || (nx == 1 && !do1)) continue;
            #pragma unroll
            for (int mt = 0; mt < 4; mt++) {
                #pragma unroll
                for (int nt = 0; nt < 4; nt++) {
                    const int q = (nx << 5) + (nt << 3) + (tig << 1);
                    #pragma unroll
                    for (int h = 0; h < 2; h++) {
                        const int k = (wm << 6) + (mt << 4) + gid + (h << 3);
                        const size_t o = nbase + (size_t)k * 4096 + prow * 64 + q;
                        float2 pv = *reinterpret_cast<const float2*>(per + o);
                        float2 ov;
                        ov.x = acc[nx][mt][nt][h * 2 + 0] + pv.x;
                        ov.y = acc[nx][mt][nt][h * 2 + 1] + pv.y;
                        *reinterpret_cast<float2*>(out + o) = ov;
                    }
                }
            }
        }

        tile = ntile; nxlo = nnxlo; nxhi = nnxhi; valid = nvalid;
    }
}

extern "C" void kernel_launch(void* const* d_in, const int* in_sizes, int n_in,
                              void* d_out, int out_size) {
    const float* x   = (const float*)d_in[0];   // (32,128,64,64)
    const float* W   = (const float*)d_in[1];   // (128,1152)
    const float* per = (const float*)d_in[2];   // (32,128,64,64)
    float* out = (float*)d_out;

    cudaFuncSetAttribute(conv_mma_kernel,
                         cudaFuncAttributeMaxDynamicSharedMemorySize, DYN_SMEM);

    prepack_kernel<<<(NSTAGES * 4096 + 255) / 256, 256>>>(W);
    conv_mma_kernel<<<SMS, 256, DYN_SMEM>>>(x, per, out);
}

// round 15
// speedup vs baseline: 1.3261x; 1.3261x over previous
#include <cuda_runtime.h>
#include <cstdint>

// ============================================================================
// tf32 mma.sync implicit-GEMM 3x3 SAME conv + bias, x-row-resident,
// A-register-reuse. R15: grid = 592 = 4*148. bids 0..431 = full tiles
// (exact R12 inner loop, NXN=2); bids 432..591 = 32-q half tiles (NXN=1,
// uniform nx offset, no per-iteration predicates) covering tiles 432..511.
// Tail wave runs cheap halves => ~0.6T instead of 1.0T.
// ============================================================================

#define NSTAGES 36

// [stage36][j4][mtile8][lane32][reg4] tf32 bits
static __device__ __align__(128) unsigned WtFrag[NSTAGES * 4 * 8 * 32 * 4];

__global__ void prepack_kernel(const float* __restrict__ W) {
    int idx = blockIdx.x * 256 + threadIdx.x;
    if (idx >= NSTAGES * 4096) return;
    int reg  = idx & 3;
    int lane = (idx >> 2) & 31;
    int mt   = (idx >> 7) & 7;
    int j    = (idx >> 10) & 3;
    int s    = idx >> 12;            // stage = shift*4 + chunk
    int shift = s >> 2;
    int chunk = s & 3;
    int dr = (reg & 1) ? 8 : 0;
    int dk = (reg & 2) ? 4 : 0;
    int r  = (lane >> 2) + dr;
    int kc = (lane & 3) + dk;
    int k  = mt * 16 + r;
    int c  = chunk * 32 + j * 8 + kc;
    float v = W[k * 1152 + c * 9 + shift];
    unsigned u;
    asm("cvt.rna.tf32.f32 %0, %1;" : "=r"(u) : "f"(v));
    WtFrag[idx] = u;
}

// x strip: [c 0..31][row 0..5][col 0..75]; data cols 4..67 (q+4), halos 3 & 68.
#define XS_PITCH  76
#define XS_ROWS   6
#define XS_BUF_F  (32 * XS_ROWS * XS_PITCH)
#define XS_BUF_B  (XS_BUF_F * 4)              // 58368 bytes
#define DYN_SMEM  (2 * XS_BUF_B)              // 116736

__device__ __forceinline__ uint32_t smem_u32(const void* p) {
    uint32_t a;
    asm("{ .reg .u64 t; cvta.to.shared.u64 t, %1; cvt.u32.u64 %0, t; }" : "=r"(a) : "l"(p));
    return a;
}

__device__ __forceinline__ void mma_tf32(float* c, const unsigned* a, const unsigned* b) {
    asm volatile(
        "mma.sync.aligned.m16n8k8.row.col.f32.tf32.tf32.f32 "
        "{%0,%1,%2,%3}, {%4,%5,%6,%7}, {%8,%9}, {%0,%1,%2,%3};"
        : "+f"(c[0]), "+f"(c[1]), "+f"(c[2]), "+f"(c[3])
        : "r"(a[0]), "r"(a[1]), "r"(a[2]), "r"(a[3]), "r"(b[0]), "r"(b[1]));
}

#define LDG_A4(dst, ptr) \
    asm volatile("ld.global.nc.v4.u32 {%0,%1,%2,%3}, [%4];" \
                 : "=r"((dst)[0]), "=r"((dst)[1]), "=r"((dst)[2]), "=r"((dst)[3]) \
                 : "l"(ptr))

// NXN = number of 32-px halves (2 = full tile, 1 = half tile at offset nxoff).
template <int NXN>
__device__ __forceinline__ void conv_body(const float* __restrict__ x,
                                          const float* __restrict__ per,
                                          float* __restrict__ out,
                                          uint32_t sb, int tile, int nxoff) {
    const int tid  = threadIdx.x;
    const int lane = tid & 31;
    const int w    = tid >> 5;
    const int wm   = w >> 2;           // 0..1 : k base wm*64
    const int wn   = w & 3;            // 0..3 : p-row index within CTA
    const int gid  = lane >> 2;        // 0..7
    const int tig  = lane & 3;         // 0..3

    const int n  = tile >> 4;
    const int p0 = (tile & 15) << 2;

    const float* xn = x + (size_t)n * 128 * 4096;

    // ---- chunk prefetch: 6 rows x 2 x 16B cp.async per thread ----
    const int f_c  = tid >> 3;
    const int f_q0 = (tid & 7) << 3;

    auto prefetch = [&](int chunk, int buf) {
        const float* srcc = xn + (size_t)((chunk << 5) + f_c) * 4096 + f_q0;
        const uint32_t dstc = sb + buf * XS_BUF_B +
                              ((f_c * XS_ROWS) * XS_PITCH + 4 + f_q0) * 4;
        #pragma unroll
        for (int r = 0; r < XS_ROWS; r++) {
            const int row = p0 - 1 + r;
            const int pb = ((unsigned)row < 64u) ? 16 : 0;
            const float* src = srcc + row * 64;
            const uint32_t dst = dstc + r * (XS_PITCH * 4);
            asm volatile("cp.async.cg.shared.global [%0], [%1], 16, %2;"
                         :: "r"(dst), "l"(src), "r"(pb));
            asm volatile("cp.async.cg.shared.global [%0], [%1], 16, %2;"
                         :: "r"(dst + 16), "l"(src + 4), "r"(pb));
        }
        asm volatile("cp.async.commit_group;");
    };

    prefetch(0, 0);
    prefetch(1, 1);

    float acc[NXN][4][4][4];
    #pragma unroll
    for (int nx = 0; nx < NXN; nx++)
        #pragma unroll
        for (int mt = 0; mt < 4; mt++)
            #pragma unroll
            for (int nt = 0; nt < 4; nt++)
                #pragma unroll
                for (int e = 0; e < 4; e++) acc[nx][mt][nt][e] = 0.f;

    const uint32_t nxbyte = (uint32_t)nxoff * 128;   // uniform half offset

    for (int chunk = 0; chunk < 4; chunk++) {
        if (chunk < 3) asm volatile("cp.async.wait_group 1;");
        else           asm volatile("cp.async.wait_group 0;");
        __syncthreads();

        const uint32_t xb = sb + (chunk & 1) * XS_BUF_B;
        const uint32_t bbase = xb + ((tig * XS_ROWS + wn) * XS_PITCH + 4 + gid) * 4
                             + nxbyte;
        const uint4* abase = (const uint4*)WtFrag + (chunk << 10) + (wm << 7) + lane;

        unsigned areg[2][4][4];
        #pragma unroll
        for (int mt = 0; mt < 4; mt++)
            LDG_A4(areg[0][mt], abase + mt * 32);

        #pragma unroll
        for (int jj = 0; jj < 36; jj++) {
            const int shift = jj >> 2, j = jj & 3;
            const int kh = shift / 3, kw = shift - 3 * kh;
            const int cur = jj & 1, nxt = cur ^ 1;

            const int jn = jj + 1;
            const int aoff = (jn >> 2) * 4096 + (jn & 3) * 256;  // uint4 units

            if (jj < 35) {
                LDG_A4(areg[nxt][0], abase + aoff + 0 * 32);
                LDG_A4(areg[nxt][1], abase + aoff + 1 * 32);
            }

            const uint32_t bsj = bbase + (kh * XS_PITCH + kw - 1) * 4 + j * 14592;

            // ---- nx = 0 (or the selected half) ----
            {
                const uint32_t bq = bsj;
                unsigned b[4][2];
                #pragma unroll
                for (int nt = 0; nt < 4; nt++) {
                    asm volatile("ld.shared.b32 %0, [%1];" : "=r"(b[nt][0])
                                 : "r"(bq + (nt << 5)));
                    asm volatile("ld.shared.b32 %0, [%1];" : "=r"(b[nt][1])
                                 : "r"(bq + (nt << 5) + 7296));   // c+4
                }
                #pragma unroll
                for (int mt = 0; mt < 4; mt++)
                    #pragma unroll
                    for (int nt = 0; nt < 4; nt++)
                        mma_tf32(acc[0][mt][nt], areg[cur][mt], b[nt]);
            }

            if (jj < 35) {
                LDG_A4(areg[nxt][2], abase + aoff + 2 * 32);
                LDG_A4(areg[nxt][3], abase + aoff + 3 * 32);
            }

            // ---- nx = 1 half (full tiles only; statically compiled) ----
            if (NXN == 2) {
                const uint32_t bq = bsj + 128;
                unsigned b[4][2];
                #pragma unroll
                for (int nt = 0; nt < 4; nt++) {
                    asm volatile("ld.shared.b32 %0, [%1];" : "=r"(b[nt][0])
                                 : "r"(bq + (nt << 5)));
                    asm volatile("ld.shared.b32 %0, [%1];" : "=r"(b[nt][1])
                                 : "r"(bq + (nt << 5) + 7296));
                }
                #pragma unroll
                for (int mt = 0; mt < 4; mt++)
                    #pragma unroll
                    for (int nt = 0; nt < 4; nt++)
                        mma_tf32(acc[NXN - 1][mt][nt], areg[cur][mt], b[nt]);
            }
        }

        __syncthreads();
        if (chunk + 2 < 4) prefetch(chunk + 2, chunk & 1);
    }

    // ---- epilogue: +perturbs, store ----
    const size_t nbase = (size_t)n * 128 * 4096;
    const int prow = p0 + wn;
    #pragma unroll
    for (int nx = 0; nx < NXN; nx++) {
        #pragma unroll
        for (int mt = 0; mt < 4; mt++) {
            #pragma unroll
            for (int nt = 0; nt < 4; nt++) {
                const int q = ((nx + nxoff) << 5) + (nt << 3) + (tig << 1);
                #pragma unroll
                for (int h = 0; h < 2; h++) {
                    const int k = (wm << 6) + (mt << 4) + gid + (h << 3);
                    const size_t o = nbase + (size_t)k * 4096 + prow * 64 + q;
                    float2 pv = *reinterpret_cast<const float2*>(per + o);
                    float2 ov;
                    ov.x = acc[nx][mt][nt][h * 2 + 0] + pv.x;
                    ov.y = acc[nx][mt][nt][h * 2 + 1] + pv.y;
                    *reinterpret_cast<float2*>(out + o) = ov;
                }
            }
        }
    }
}

__global__ __launch_bounds__(256, 1)
void conv_mma_kernel(const float* __restrict__ x,
                     const float* __restrict__ per,
                     float* __restrict__ out) {
    extern __shared__ char smem[];
    const uint32_t sb = smem_u32(smem);
    const int tid = threadIdx.x;
    const int bid = blockIdx.x;

    // ---- zero halo columns (cols 3 and 68 of every (c,row), both buffers) ----
    for (int idx = tid; idx < 2 * 32 * XS_ROWS; idx += 256) {
        const int buf = idx >= 32 * XS_ROWS;
        const int rem = buf ? idx - 32 * XS_ROWS : idx;
        const uint32_t a = sb + buf * XS_BUF_B + rem * (XS_PITCH * 4);
        asm volatile("st.shared.f32 [%0], %1;" :: "r"(a + 3 * 4), "f"(0.f));
        asm volatile("st.shared.f32 [%0], %1;" :: "r"(a + 68 * 4), "f"(0.f));
    }

    if (bid < 432) {
        conv_body<2>(x, per, out, sb, bid, 0);
    } else {
        const int h = bid - 432;                 // 0..159
        conv_body<1>(x, per, out, sb, 432 + (h >> 1), h & 1);
    }
}

extern "C" void kernel_launch(void* const* d_in, const int* in_sizes, int n_in,
                              void* d_out, int out_size) {
    const float* x   = (const float*)d_in[0];   // (32,128,64,64)
    const float* W   = (const float*)d_in[1];   // (128,1152)
    const float* per = (const float*)d_in[2];   // (32,128,64,64)
    float* out = (float*)d_out;

    cudaFuncSetAttribute(conv_mma_kernel,
                         cudaFuncAttributeMaxDynamicSharedMemorySize, DYN_SMEM);

    prepack_kernel<<<(NSTAGES * 4096 + 255) / 256, 256>>>(W);
    conv_mma_kernel<<<592, 256, DYN_SMEM>>>(x, per, out);
}

// round 16
// speedup vs baseline: 1.3279x; 1.0013x over previous
#include <cuda_runtime.h>
#include <cstdint>

// ============================================================================
// tf32 mma.sync implicit-GEMM 3x3 SAME conv + bias, x-row-resident,
// A-register-reuse. R16: BOTH operands software-pipelined — A(jj+1) and
// B(jj+1) loaded into next-buffers at jj top, MMAs consume cur buffers with
// no intra-jj scoreboard waits. Grid = 592 = 4*148: bids 0..431 full tiles,
// 432..591 32-q half tiles (tail wave ~0.6T).
// ============================================================================

#define NSTAGES 36

// [stage36][j4][mtile8][lane32][reg4] tf32 bits
static __device__ __align__(128) unsigned WtFrag[NSTAGES * 4 * 8 * 32 * 4];

__global__ void prepack_kernel(const float* __restrict__ W) {
    int idx = blockIdx.x * 256 + threadIdx.x;
    if (idx >= NSTAGES * 4096) return;
    int reg  = idx & 3;
    int lane = (idx >> 2) & 31;
    int mt   = (idx >> 7) & 7;
    int j    = (idx >> 10) & 3;
    int s    = idx >> 12;            // stage = shift*4 + chunk
    int shift = s >> 2;
    int chunk = s & 3;
    int dr = (reg & 1) ? 8 : 0;
    int dk = (reg & 2) ? 4 : 0;
    int r  = (lane >> 2) + dr;
    int kc = (lane & 3) + dk;
    int k  = mt * 16 + r;
    int c  = chunk * 32 + j * 8 + kc;
    float v = W[k * 1152 + c * 9 + shift];
    unsigned u;
    asm("cvt.rna.tf32.f32 %0, %1;" : "=r"(u) : "f"(v));
    WtFrag[idx] = u;
}

// x strip: [c 0..31][row 0..5][col 0..75]; data cols 4..67 (q+4), halos 3 & 68.
#define XS_PITCH  76
#define XS_ROWS   6
#define XS_BUF_F  (32 * XS_ROWS * XS_PITCH)
#define XS_BUF_B  (XS_BUF_F * 4)              // 58368 bytes
#define DYN_SMEM  (2 * XS_BUF_B)              // 116736

__device__ __forceinline__ uint32_t smem_u32(const void* p) {
    uint32_t a;
    asm("{ .reg .u64 t; cvta.to.shared.u64 t, %1; cvt.u32.u64 %0, t; }" : "=r"(a) : "l"(p));
    return a;
}

__device__ __forceinline__ void mma_tf32(float* c, const unsigned* a, const unsigned* b) {
    asm volatile(
        "mma.sync.aligned.m16n8k8.row.col.f32.tf32.tf32.f32 "
        "{%0,%1,%2,%3}, {%4,%5,%6,%7}, {%8,%9}, {%0,%1,%2,%3};"
        : "+f"(c[0]), "+f"(c[1]), "+f"(c[2]), "+f"(c[3])
        : "r"(a[0]), "r"(a[1]), "r"(a[2]), "r"(a[3]), "r"(b[0]), "r"(b[1]));
}

#define LDG_A4(dst, ptr) \
    asm volatile("ld.global.nc.v4.u32 {%0,%1,%2,%3}, [%4];" \
                 : "=r"((dst)[0]), "=r"((dst)[1]), "=r"((dst)[2]), "=r"((dst)[3]) \
                 : "l"(ptr))

#define LDB(dst, addr) \
    asm volatile("ld.shared.b32 %0, [%1];" : "=r"(dst) : "r"(addr))

// NXN = number of 32-px halves (2 = full tile, 1 = half tile at offset nxoff).
template <int NXN>
__device__ __forceinline__ void conv_body(const float* __restrict__ x,
                                          const float* __restrict__ per,
                                          float* __restrict__ out,
                                          uint32_t sb, int tile, int nxoff) {
    const int tid  = threadIdx.x;
    const int lane = tid & 31;
    const int w    = tid >> 5;
    const int wm   = w >> 2;           // 0..1 : k base wm*64
    const int wn   = w & 3;            // 0..3 : p-row index within CTA
    const int gid  = lane >> 2;        // 0..7
    const int tig  = lane & 3;         // 0..3

    const int n  = tile >> 4;
    const int p0 = (tile & 15) << 2;

    const float* xn = x + (size_t)n * 128 * 4096;

    // ---- chunk prefetch: 6 rows x 2 x 16B cp.async per thread ----
    const int f_c  = tid >> 3;
    const int f_q0 = (tid & 7) << 3;

    auto prefetch = [&](int chunk, int buf) {
        const float* srcc = xn + (size_t)((chunk << 5) + f_c) * 4096 + f_q0;
        const uint32_t dstc = sb + buf * XS_BUF_B +
                              ((f_c * XS_ROWS) * XS_PITCH + 4 + f_q0) * 4;
        #pragma unroll
        for (int r = 0; r < XS_ROWS; r++) {
            const int row = p0 - 1 + r;
            const int pb = ((unsigned)row < 64u) ? 16 : 0;
            const float* src = srcc + row * 64;
            const uint32_t dst = dstc + r * (XS_PITCH * 4);
            asm volatile("cp.async.cg.shared.global [%0], [%1], 16, %2;"
                         :: "r"(dst), "l"(src), "r"(pb));
            asm volatile("cp.async.cg.shared.global [%0], [%1], 16, %2;"
                         :: "r"(dst + 16), "l"(src + 4), "r"(pb));
        }
        asm volatile("cp.async.commit_group;");
    };

    prefetch(0, 0);
    prefetch(1, 1);

    float acc[NXN][4][4][4];
    #pragma unroll
    for (int nx = 0; nx < NXN; nx++)
        #pragma unroll
        for (int mt = 0; mt < 4; mt++)
            #pragma unroll
            for (int nt = 0; nt < 4; nt++)
                #pragma unroll
                for (int e = 0; e < 4; e++) acc[nx][mt][nt][e] = 0.f;

    const uint32_t nxbyte = (uint32_t)nxoff * 128;   // uniform half offset

    for (int chunk = 0; chunk < 4; chunk++) {
        if (chunk < 3) asm volatile("cp.async.wait_group 1;");
        else           asm volatile("cp.async.wait_group 0;");
        __syncthreads();

        const uint32_t xb = sb + (chunk & 1) * XS_BUF_B;
        const uint32_t bbase = xb + ((tig * XS_ROWS + wn) * XS_PITCH + 4 + gid) * 4
                             + nxbyte;
        const uint4* abase = (const uint4*)WtFrag + (chunk << 10) + (wm << 7) + lane;

        unsigned areg[2][4][4];
        unsigned breg[2][NXN][4][2];

        // ---- prologue: load jj=0 operands (shift=0: kh=0, kw=0, j=0) ----
        #pragma unroll
        for (int mt = 0; mt < 4; mt++)
            LDG_A4(areg[0][mt], abase + mt * 32);
        {
            const uint32_t bsj0 = bbase - 4;    // (0*76 + 0 - 1)*4
            #pragma unroll
            for (int nx = 0; nx < NXN; nx++)
                #pragma unroll
                for (int nt = 0; nt < 4; nt++) {
                    LDB(breg[0][nx][nt][0], bsj0 + nx * 128 + (nt << 5));
                    LDB(breg[0][nx][nt][1], bsj0 + nx * 128 + (nt << 5) + 7296);
                }
        }

        #pragma unroll
        for (int jj = 0; jj < 36; jj++) {
            const int cur = jj & 1, nxt = cur ^ 1;

            // ---- prefetch jj+1 operands into next buffers ----
            if (jj < 35) {
                const int jn = jj + 1;
                const int aoff = (jn >> 2) * 4096 + (jn & 3) * 256;  // uint4 units
                #pragma unroll
                for (int mt = 0; mt < 4; mt++)
                    LDG_A4(areg[nxt][mt], abase + aoff + mt * 32);

                const int sh = jn >> 2, jB = jn & 3;
                const int kh = sh / 3, kw = sh - 3 * kh;
                const uint32_t bsj = bbase + (kh * XS_PITCH + kw - 1) * 4 + jB * 14592;
                #pragma unroll
                for (int nx = 0; nx < NXN; nx++)
                    #pragma unroll
                    for (int nt = 0; nt < 4; nt++) {
                        LDB(breg[nxt][nx][nt][0], bsj + nx * 128 + (nt << 5));
                        LDB(breg[nxt][nx][nt][1], bsj + nx * 128 + (nt << 5) + 7296);
                    }
            }

            // ---- MMAs on current buffers (no intra-jj dependencies) ----
            #pragma unroll
            for (int nx = 0; nx < NXN; nx++)
                #pragma unroll
                for (int mt = 0; mt < 4; mt++)
                    #pragma unroll
                    for (int nt = 0; nt < 4; nt++)
                        mma_tf32(acc[nx][mt][nt], areg[cur][mt], breg[cur][nx][nt]);
        }

        __syncthreads();
        if (chunk + 2 < 4) prefetch(chunk + 2, chunk & 1);
    }

    // ---- epilogue: +perturbs, store ----
    const size_t nbase = (size_t)n * 128 * 4096;
    const int prow = p0 + wn;
    #pragma unroll
    for (int nx = 0; nx < NXN; nx++) {
        #pragma unroll
        for (int mt = 0; mt < 4; mt++) {
            #pragma unroll
            for (int nt = 0; nt < 4; nt++) {
                const int q = ((nx + nxoff) << 5) + (nt << 3) + (tig << 1);
                #pragma unroll
                for (int h = 0; h < 2; h++) {
                    const int k = (wm << 6) + (mt << 4) + gid + (h << 3);
                    const size_t o = nbase + (size_t)k * 4096 + prow * 64 + q;
                    float2 pv = *reinterpret_cast<const float2*>(per + o);
                    float2 ov;
                    ov.x = acc[nx][mt][nt][h * 2 + 0] + pv.x;
                    ov.y = acc[nx][mt][nt][h * 2 + 1] + pv.y;
                    *reinterpret_cast<float2*>(out + o) = ov;
                }
            }
        }
    }
}

__global__ __launch_bounds__(256, 1)
void conv_mma_kernel(const float* __restrict__ x,
                     const float* __restrict__ per,
                     float* __restrict__ out) {
    extern __shared__ char smem[];
    const uint32_t sb = smem_u32(smem);
    const int tid = threadIdx.x;
    const int bid = blockIdx.x;

    // ---- zero halo columns (cols 3 and 68 of every (c,row), both buffers) ----
    for (int idx = tid; idx < 2 * 32 * XS_ROWS; idx += 256) {
        const int buf = idx >= 32 * XS_ROWS;
        const int rem = buf ? idx - 32 * XS_ROWS : idx;
        const uint32_t a = sb + buf * XS_BUF_B + rem * (XS_PITCH * 4);
        asm volatile("st.shared.f32 [%0], %1;" :: "r"(a + 3 * 4), "f"(0.f));
        asm volatile("st.shared.f32 [%0], %1;" :: "r"(a + 68 * 4), "f"(0.f));
    }

    if (bid < 432) {
        conv_body<2>(x, per, out, sb, bid, 0);
    } else {
        const int h = bid - 432;                 // 0..159
        conv_body<1>(x, per, out, sb, 432 + (h >> 1), h & 1);
    }
}

extern "C" void kernel_launch(void* const* d_in, const int* in_sizes, int n_in,
                              void* d_out, int out_size) {
    const float* x   = (const float*)d_in[0];   // (32,128,64,64)
    const float* W   = (const float*)d_in[1];   // (128,1152)
    const float* per = (const float*)d_in[2];   // (32,128,64,64)
    float* out = (float*)d_out;

    cudaFuncSetAttribute(conv_mma_kernel,
                         cudaFuncAttributeMaxDynamicSharedMemorySize, DYN_SMEM);

    prepack_kernel<<<(NSTAGES * 4096 + 255) / 256, 256>>>(W);
    conv_mma_kernel<<<592, 256, DYN_SMEM>>>(x, per, out);
}